// round 14
// baseline (speedup 1.0000x reference)
#include <cuda_runtime.h>

#define B_ 16
#define A_ 5
#define C_ 512
#define HW_ 256
#define NC 4
#define CCHUNK 32
#define NX (C_ / CCHUNK)          // 16 channel-chunks
#define NT (NX * A_ * B_)         // 1280 tiles
#define GRID_P 304                // persistent CTAs (2 per SM, 152 SMs)
#define SMEM_BYTES (64 * 1024)

// out[(i*B+b)] = local[(i*B+b)] + sum_{j != i, j<n, i<n} warp(local[(j*B+b)], trans[b,i,j])
// warp = bilinear grid_sample chained twice (rotation, then constant translation),
// zero pad, align_corners=False. Geometry channel-invariant -> register tap tables.
// float4 channel-vectorized tiles; cross-chunk software pipeline (stage2 of chunk
// k-1 in iteration k, both tiles ping-pong) -> ONE __syncthreads per chunk.
// R14: persistent CTAs + atomic tile queue -> no wave tail, heavy/light tiles
// self-balance. Counter self-resets on the last failed grab (graph-replay safe).

extern __shared__ float4 sm4[];
// tileA: [2][4][256] float4 at offset 0      (32KB)
// tileR: [2][4][256] float4 at offset 2048   (32KB)

__device__ unsigned g_tile_ctr = 0;

__global__ __launch_bounds__(256, 2)
void fuse_kernel(const float* __restrict__ feat,
                 const float* __restrict__ trans,
                 const int* __restrict__ nag,
                 float* __restrict__ out)
{
    float4* __restrict__ tileA = sm4;
    float4* __restrict__ tileR = sm4 + 2048;

    __shared__ unsigned s_tile;

    const int t = threadIdx.x;
    const int x = t & 15;
    const int y = t >> 4;
    const float xs = (2.f * (float)x + 1.f) / 16.f - 1.f;
    const float ys = (2.f * (float)y + 1.f) / 16.f - 1.f;

    for (;;) {
        if (t == 0) s_tile = atomicAdd(&g_tile_ctr, 1u);
        __syncthreads();
        const unsigned tile = s_tile;
        if (tile >= NT) {
            // last failed grab resets the counter for the next launch/replay
            if (t == 0 && tile == NT + GRID_P - 1) g_tile_ctr = 0;
            break;
        }

        // decode: (b,i) fastest -> consecutive tiles mix agent loads;
        // 80-tile slabs share a channel range (L2-friendly)
        const int bi = (int)(tile % (A_ * B_));
        const int c0 = (int)(tile / (A_ * B_)) * CCHUNK;
        const int b  = bi % B_;
        const int i  = bi / B_;

        const int n = nag[b * A_];            // num_agent_tensor[b, 0]
        const bool active = (i < n) && (n > 1);

        const unsigned base = ((unsigned)(i * B_ + b) * C_ + c0) * HW_;
        const float* __restrict__ local = feat + base;
        float* __restrict__ outp        = out  + base;

        // ---- neighbor offsets + validity, then issue chunk-0 LDGs early ----
        unsigned off[4];
        bool valid[4];
        #pragma unroll
        for (int jj = 0; jj < 4; jj++) {
            const int j = jj + (jj >= i ? 1 : 0);          // skip j == i
            valid[jj] = active && (j < n);
            off[jj]   = ((unsigned)(j * B_ + b) * C_ + c0) * HW_;
        }

        float4 pre[4];
        #pragma unroll
        for (int jj = 0; jj < 4; jj++) {
            if (valid[jj]) {
                const float* src = feat + off[jj];
                pre[jj].x = src[t];
                pre[jj].y = src[HW_ + t];
                pre[jj].z = src[2 * HW_ + t];
                pre[jj].w = src[3 * HW_ + t];
            }
        }

        // ---- tap tables (ALU hides the LDGs above) ----
        float    wA[4][4], wB[4][4];
        unsigned pA[4], pB[4];

        #pragma unroll
        for (int jj = 0; jj < 4; jj++) {
            const int j = jj + (jj >= i ? 1 : 0);
            pA[jj] = 0u; pB[jj] = 0u;
            #pragma unroll
            for (int m = 0; m < 4; m++) { wA[jj][m] = 0.f; wB[jj][m] = 0.f; }
            if (valid[jj]) {
                const float* T = trans + (((b * A_ + i) * A_ + j) * 16);
                const float t00 = T[0], t01 = T[1], t03 = T[3];
                const float t10 = T[4], t11 = T[5], t13 = T[7];

                // ---- stage 1: rotation grid ----
                const float gx = t00 * xs + t01 * ys;
                const float gy = t10 * xs + t11 * ys;
                const float ix = ((gx + 1.f) * 16.f - 1.f) * 0.5f;
                const float iy = ((gy + 1.f) * 16.f - 1.f) * 0.5f;
                const float x0f = floorf(ix), y0f = floorf(iy);
                const float fx = ix - x0f,  fy = iy - y0f;
                const int x0 = (int)x0f, y0 = (int)y0f;
                #pragma unroll
                for (int m = 0; m < 4; m++) {
                    const int dx = m & 1, dy = m >> 1;
                    const int xi = x0 + dx, yi = y0 + dy;
                    const float w = (dx ? fx : 1.f - fx) * (dy ? fy : 1.f - fy);
                    const bool in = (xi >= 0) & (xi < 16) & (yi >= 0) & (yi < 16);
                    wA[jj][m] = in ? w : 0.f;
                    pA[jj]  |= (unsigned)(in ? (yi * 16 + xi) : 0) << (8 * m);
                }

                // ---- stage 2: translation grid ----
                const float xt = t03 * (1.f / 32.f);      // 4*T03/128
                const float yt = -t13 * (1.f / 32.f);
                const float ix2 = ((xs + xt + 1.f) * 16.f - 1.f) * 0.5f;
                const float iy2 = ((ys + yt + 1.f) * 16.f - 1.f) * 0.5f;
                const float x20f = floorf(ix2), y20f = floorf(iy2);
                const float fx2 = ix2 - x20f,  fy2 = iy2 - y20f;
                const int x20 = (int)x20f, y20 = (int)y20f;
                #pragma unroll
                for (int m = 0; m < 4; m++) {
                    const int dx = m & 1, dy = m >> 1;
                    const int xi = x20 + dx, yi = y20 + dy;
                    const float w = (dx ? fx2 : 1.f - fx2) * (dy ? fy2 : 1.f - fy2);
                    const bool in = (xi >= 0) & (xi < 16) & (yi >= 0) & (yi < 16);
                    wB[jj][m] = in ? w : 0.f;
                    pB[jj]  |= (unsigned)(in ? (yi * 16 + xi) : 0) << (8 * m);
                }
            }
        }

        // ---- pipelined main loop: one __syncthreads per chunk ----
        float4 accP;
        int gP = 0;

        for (int k = 0, g = 0; g < CCHUNK; g += NC, k++) {
            const int p = k & 1;
            #pragma unroll
            for (int jj = 0; jj < 4; jj++) {
                if (valid[jj]) tileA[(p * 4 + jj) * 256 + t] = pre[jj];
            }

            float4 accC;
            accC.x = local[(g + 0) * HW_ + t];
            accC.y = local[(g + 1) * HW_ + t];
            accC.z = local[(g + 2) * HW_ + t];
            accC.w = local[(g + 3) * HW_ + t];

            __syncthreads();   // tileA[p] RAW (chunk k), tileR[p^1] RAW (chunk k-1)

            if (g + NC < CCHUNK) {
                #pragma unroll
                for (int jj = 0; jj < 4; jj++) {
                    if (valid[jj]) {
                        const float* src = feat + off[jj] + (unsigned)(g + NC) * HW_;
                        pre[jj].x = src[t];
                        pre[jj].y = src[HW_ + t];
                        pre[jj].z = src[2 * HW_ + t];
                        pre[jj].w = src[3 * HW_ + t];
                    }
                }
            }

            // stage 1 (chunk k): rotation sample tileA[p] -> tileR[p]
            #pragma unroll
            for (int jj = 0; jj < 4; jj++) {
                if (valid[jj]) {
                    const int tb = (p * 4 + jj) * 256;
                    const float4 v0 = tileA[tb + ((pA[jj]      ) & 255)];
                    const float4 v1 = tileA[tb + ((pA[jj] >>  8) & 255)];
                    const float4 v2 = tileA[tb + ((pA[jj] >> 16) & 255)];
                    const float4 v3 = tileA[tb + ((pA[jj] >> 24) & 255)];
                    const float w0 = wA[jj][0], w1 = wA[jj][1], w2 = wA[jj][2], w3 = wA[jj][3];
                    float4 r;
                    r.x = w0 * v0.x + w1 * v1.x + w2 * v2.x + w3 * v3.x;
                    r.y = w0 * v0.y + w1 * v1.y + w2 * v2.y + w3 * v3.y;
                    r.z = w0 * v0.z + w1 * v1.z + w2 * v2.z + w3 * v3.z;
                    r.w = w0 * v0.w + w1 * v1.w + w2 * v2.w + w3 * v3.w;
                    tileR[(p * 4 + jj) * 256 + t] = r;
                }
            }

            // stage 2 (chunk k-1): translation sample tileR[p^1] -> accumulate + store
            if (k > 0) {
                const int q = (k - 1) & 1;
                #pragma unroll
                for (int jj = 0; jj < 4; jj++) {
                    if (valid[jj]) {
                        const int rb = (q * 4 + jj) * 256;
                        const float4 v0 = tileR[rb + ((pB[jj]      ) & 255)];
                        const float4 v1 = tileR[rb + ((pB[jj] >>  8) & 255)];
                        const float4 v2 = tileR[rb + ((pB[jj] >> 16) & 255)];
                        const float4 v3 = tileR[rb + ((pB[jj] >> 24) & 255)];
                        const float w0 = wB[jj][0], w1 = wB[jj][1], w2 = wB[jj][2], w3 = wB[jj][3];
                        accP.x += w0 * v0.x + w1 * v1.x + w2 * v2.x + w3 * v3.x;
                        accP.y += w0 * v0.y + w1 * v1.y + w2 * v2.y + w3 * v3.y;
                        accP.z += w0 * v0.z + w1 * v1.z + w2 * v2.z + w3 * v3.z;
                        accP.w += w0 * v0.w + w1 * v1.w + w2 * v2.w + w3 * v3.w;
                    }
                }
                __stcs(&outp[(gP + 0) * HW_ + t], accP.x);
                __stcs(&outp[(gP + 1) * HW_ + t], accP.y);
                __stcs(&outp[(gP + 2) * HW_ + t], accP.z);
                __stcs(&outp[(gP + 3) * HW_ + t], accP.w);
            }
            accP = accC;
            gP = g;
        }

        // ---- epilogue: drain stage 2 of the last chunk ----
        __syncthreads();
        {
            const int q = ((CCHUNK / NC) - 1) & 1;
            #pragma unroll
            for (int jj = 0; jj < 4; jj++) {
                if (valid[jj]) {
                    const int rb = (q * 4 + jj) * 256;
                    const float4 v0 = tileR[rb + ((pB[jj]      ) & 255)];
                    const float4 v1 = tileR[rb + ((pB[jj] >>  8) & 255)];
                    const float4 v2 = tileR[rb + ((pB[jj] >> 16) & 255)];
                    const float4 v3 = tileR[rb + ((pB[jj] >> 24) & 255)];
                    const float w0 = wB[jj][0], w1 = wB[jj][1], w2 = wB[jj][2], w3 = wB[jj][3];
                    accP.x += w0 * v0.x + w1 * v1.x + w2 * v2.x + w3 * v3.x;
                    accP.y += w0 * v0.y + w1 * v1.y + w2 * v2.y + w3 * v3.y;
                    accP.z += w0 * v0.z + w1 * v1.z + w2 * v2.z + w3 * v3.z;
                    accP.w += w0 * v0.w + w1 * v1.w + w2 * v2.w + w3 * v3.w;
                }
            }
            __stcs(&outp[(gP + 0) * HW_ + t], accP.x);
            __stcs(&outp[(gP + 1) * HW_ + t], accP.y);
            __stcs(&outp[(gP + 2) * HW_ + t], accP.z);
            __stcs(&outp[(gP + 3) * HW_ + t], accP.w);
        }
        // next iteration's s_tile overwrite is ordered after all reads by the
        // body's __syncthreads chain (present even on copy-only tiles)
    }
}

extern "C" void kernel_launch(void* const* d_in, const int* in_sizes, int n_in,
                              void* d_out, int out_size)
{
    const float* feat  = (const float*)d_in[0];   // [A*B, C, H, W] f32
    const float* trans = (const float*)d_in[1];   // [B, A, A, 4, 4] f32
    const int*   nag   = (const int*)d_in[2];     // [B, A] int32
    float* out = (float*)d_out;                   // [A*B, C, H, W] f32

    static int attr_set = 0;
    if (!attr_set) {
        cudaFuncSetAttribute(fuse_kernel,
                             cudaFuncAttributeMaxDynamicSharedMemorySize, SMEM_BYTES);
        attr_set = 1;
    }

    fuse_kernel<<<GRID_P, 256, SMEM_BYTES>>>(feat, trans, nag, out);
}

// round 15
// speedup vs baseline: 1.0057x; 1.0057x over previous
#include <cuda_runtime.h>

#define B_ 16
#define A_ 5
#define C_ 512
#define HW_ 256
#define NC 4
#define CCHUNK 32
#define SMEM_BYTES (64 * 1024)

// out[(i*B+b)] = local[(i*B+b)] + sum_{j != i, j<n, i<n} warp(local[(j*B+b)], trans[b,i,j])
// warp = bilinear grid_sample chained twice (rotation, then constant translation),
// zero pad, align_corners=False. Geometry channel-invariant -> register tap tables.
// float4 channel-vectorized tiles; cross-chunk software pipeline (stage2 of chunk
// k-1 in iteration k, both tiles ping-pong) -> ONE __syncthreads per chunk.
// R15: block-uniform fast path — copy-only blocks (i>=n or n==1, ~44% of blocks)
// do a pure float4 streaming copy with no barriers/smem/tap ALU.

extern __shared__ float4 sm4[];
// tileA: [2][4][256] float4 at offset 0      (32KB)
// tileR: [2][4][256] float4 at offset 2048   (32KB)

__global__ __launch_bounds__(256, 2)
void fuse_kernel(const float* __restrict__ feat,
                 const float* __restrict__ trans,
                 const int* __restrict__ nag,
                 float* __restrict__ out)
{
    float4* __restrict__ tileA = sm4;
    float4* __restrict__ tileR = sm4 + 2048;

    const int b  = blockIdx.z;
    const int i  = blockIdx.y;
    const int c0 = blockIdx.x * CCHUNK;
    const int t  = threadIdx.x;

    const int n = nag[b * A_];            // num_agent_tensor[b, 0]
    const bool active = (i < n) && (n > 1);

    const unsigned base = ((unsigned)(i * B_ + b) * C_ + c0) * HW_;
    const float* __restrict__ local = feat + base;
    float* __restrict__ outp        = out  + base;

    // ---- fast path: copy-only block (block-uniform branch; no barriers used) ----
    if (!active) {
        const float4* __restrict__ s4 = (const float4*)local;
        float4* __restrict__ d4       = (float4*)outp;
        #pragma unroll
        for (int k = 0; k < (CCHUNK * HW_ / 4) / 256; k++) {   // 8 iters
            const float4 v = __ldcs(&s4[k * 256 + t]);
            __stcs(&d4[k * 256 + t], v);
        }
        return;
    }

    const int x = t & 15;
    const int y = t >> 4;

    // ---- neighbor offsets + validity, then issue chunk-0 LDGs early ----
    unsigned off[4];
    bool valid[4];
    #pragma unroll
    for (int jj = 0; jj < 4; jj++) {
        const int j = jj + (jj >= i ? 1 : 0);          // skip j == i
        valid[jj] = (j < n);
        off[jj]   = ((unsigned)(j * B_ + b) * C_ + c0) * HW_;
    }

    float4 pre[4];
    #pragma unroll
    for (int jj = 0; jj < 4; jj++) {
        if (valid[jj]) {
            const float* src = feat + off[jj];
            pre[jj].x = src[t];
            pre[jj].y = src[HW_ + t];
            pre[jj].z = src[2 * HW_ + t];
            pre[jj].w = src[3 * HW_ + t];
        }
    }

    // ---- tap tables (ALU hides the LDGs above) ----
    const float xs = (2.f * (float)x + 1.f) / 16.f - 1.f;
    const float ys = (2.f * (float)y + 1.f) / 16.f - 1.f;

    float    wA[4][4], wB[4][4];
    unsigned pA[4], pB[4];                // 4 byte-indices packed per table

    #pragma unroll
    for (int jj = 0; jj < 4; jj++) {
        const int j = jj + (jj >= i ? 1 : 0);
        pA[jj] = 0u; pB[jj] = 0u;
        #pragma unroll
        for (int m = 0; m < 4; m++) { wA[jj][m] = 0.f; wB[jj][m] = 0.f; }
        if (valid[jj]) {
            const float* T = trans + (((b * A_ + i) * A_ + j) * 16);
            const float t00 = T[0], t01 = T[1], t03 = T[3];
            const float t10 = T[4], t11 = T[5], t13 = T[7];

            // ---- stage 1: rotation grid ----
            const float gx = t00 * xs + t01 * ys;
            const float gy = t10 * xs + t11 * ys;
            const float ix = ((gx + 1.f) * 16.f - 1.f) * 0.5f;
            const float iy = ((gy + 1.f) * 16.f - 1.f) * 0.5f;
            const float x0f = floorf(ix), y0f = floorf(iy);
            const float fx = ix - x0f,  fy = iy - y0f;
            const int x0 = (int)x0f, y0 = (int)y0f;
            #pragma unroll
            for (int m = 0; m < 4; m++) {
                const int dx = m & 1, dy = m >> 1;
                const int xi = x0 + dx, yi = y0 + dy;
                const float w = (dx ? fx : 1.f - fx) * (dy ? fy : 1.f - fy);
                const bool in = (xi >= 0) & (xi < 16) & (yi >= 0) & (yi < 16);
                wA[jj][m] = in ? w : 0.f;
                pA[jj]  |= (unsigned)(in ? (yi * 16 + xi) : 0) << (8 * m);
            }

            // ---- stage 2: translation grid ----
            const float xt = t03 * (1.f / 32.f);      // 4*T03/128
            const float yt = -t13 * (1.f / 32.f);
            const float ix2 = ((xs + xt + 1.f) * 16.f - 1.f) * 0.5f;
            const float iy2 = ((ys + yt + 1.f) * 16.f - 1.f) * 0.5f;
            const float x20f = floorf(ix2), y20f = floorf(iy2);
            const float fx2 = ix2 - x20f,  fy2 = iy2 - y20f;
            const int x20 = (int)x20f, y20 = (int)y20f;
            #pragma unroll
            for (int m = 0; m < 4; m++) {
                const int dx = m & 1, dy = m >> 1;
                const int xi = x20 + dx, yi = y20 + dy;
                const float w = (dx ? fx2 : 1.f - fx2) * (dy ? fy2 : 1.f - fy2);
                const bool in = (xi >= 0) & (xi < 16) & (yi >= 0) & (yi < 16);
                wB[jj][m] = in ? w : 0.f;
                pB[jj]  |= (unsigned)(in ? (yi * 16 + xi) : 0) << (8 * m);
            }
        }
    }

    // ---- pipelined main loop: one __syncthreads per chunk ----
    float4 accP;                          // accumulator of the previous chunk
    int gP = 0;

    for (int k = 0, g = 0; g < CCHUNK; g += NC, k++) {
        const int p = k & 1;
        // deposit prefetched fills (STS.128, conflict-free)
        #pragma unroll
        for (int jj = 0; jj < 4; jj++) {
            if (valid[jj]) tileA[(p * 4 + jj) * 256 + t] = pre[jj];
        }

        float4 accC;
        accC.x = local[(g + 0) * HW_ + t];
        accC.y = local[(g + 1) * HW_ + t];
        accC.z = local[(g + 2) * HW_ + t];
        accC.w = local[(g + 3) * HW_ + t];

        __syncthreads();   // tileA[p] RAW (chunk k), tileR[p^1] RAW (chunk k-1)

        // prefetch next chunk's fills
        if (g + NC < CCHUNK) {
            #pragma unroll
            for (int jj = 0; jj < 4; jj++) {
                if (valid[jj]) {
                    const float* src = feat + off[jj] + (unsigned)(g + NC) * HW_;
                    pre[jj].x = src[t];
                    pre[jj].y = src[HW_ + t];
                    pre[jj].z = src[2 * HW_ + t];
                    pre[jj].w = src[3 * HW_ + t];
                }
            }
        }

        // stage 1 (chunk k): rotation sample tileA[p] -> tileR[p]
        #pragma unroll
        for (int jj = 0; jj < 4; jj++) {
            if (valid[jj]) {
                const int tb = (p * 4 + jj) * 256;
                const float4 v0 = tileA[tb + ((pA[jj]      ) & 255)];
                const float4 v1 = tileA[tb + ((pA[jj] >>  8) & 255)];
                const float4 v2 = tileA[tb + ((pA[jj] >> 16) & 255)];
                const float4 v3 = tileA[tb + ((pA[jj] >> 24) & 255)];
                const float w0 = wA[jj][0], w1 = wA[jj][1], w2 = wA[jj][2], w3 = wA[jj][3];
                float4 r;
                r.x = w0 * v0.x + w1 * v1.x + w2 * v2.x + w3 * v3.x;
                r.y = w0 * v0.y + w1 * v1.y + w2 * v2.y + w3 * v3.y;
                r.z = w0 * v0.z + w1 * v1.z + w2 * v2.z + w3 * v3.z;
                r.w = w0 * v0.w + w1 * v1.w + w2 * v2.w + w3 * v3.w;
                tileR[(p * 4 + jj) * 256 + t] = r;
            }
        }

        // stage 2 (chunk k-1): translation sample tileR[p^1] -> accumulate + store
        if (k > 0) {
            const int q = (k - 1) & 1;
            #pragma unroll
            for (int jj = 0; jj < 4; jj++) {
                if (valid[jj]) {
                    const int rb = (q * 4 + jj) * 256;
                    const float4 v0 = tileR[rb + ((pB[jj]      ) & 255)];
                    const float4 v1 = tileR[rb + ((pB[jj] >>  8) & 255)];
                    const float4 v2 = tileR[rb + ((pB[jj] >> 16) & 255)];
                    const float4 v3 = tileR[rb + ((pB[jj] >> 24) & 255)];
                    const float w0 = wB[jj][0], w1 = wB[jj][1], w2 = wB[jj][2], w3 = wB[jj][3];
                    accP.x += w0 * v0.x + w1 * v1.x + w2 * v2.x + w3 * v3.x;
                    accP.y += w0 * v0.y + w1 * v1.y + w2 * v2.y + w3 * v3.y;
                    accP.z += w0 * v0.z + w1 * v1.z + w2 * v2.z + w3 * v3.z;
                    accP.w += w0 * v0.w + w1 * v1.w + w2 * v2.w + w3 * v3.w;
                }
            }
            __stcs(&outp[(gP + 0) * HW_ + t], accP.x);
            __stcs(&outp[(gP + 1) * HW_ + t], accP.y);
            __stcs(&outp[(gP + 2) * HW_ + t], accP.z);
            __stcs(&outp[(gP + 3) * HW_ + t], accP.w);
        }
        accP = accC;
        gP = g;
    }

    // ---- epilogue: drain stage 2 of the last chunk ----
    __syncthreads();
    {
        const int q = ((CCHUNK / NC) - 1) & 1;
        #pragma unroll
        for (int jj = 0; jj < 4; jj++) {
            if (valid[jj]) {
                const int rb = (q * 4 + jj) * 256;
                const float4 v0 = tileR[rb + ((pB[jj]      ) & 255)];
                const float4 v1 = tileR[rb + ((pB[jj] >>  8) & 255)];
                const float4 v2 = tileR[rb + ((pB[jj] >> 16) & 255)];
                const float4 v3 = tileR[rb + ((pB[jj] >> 24) & 255)];
                const float w0 = wB[jj][0], w1 = wB[jj][1], w2 = wB[jj][2], w3 = wB[jj][3];
                accP.x += w0 * v0.x + w1 * v1.x + w2 * v2.x + w3 * v3.x;
                accP.y += w0 * v0.y + w1 * v1.y + w2 * v2.y + w3 * v3.y;
                accP.z += w0 * v0.z + w1 * v1.z + w2 * v2.z + w3 * v3.z;
                accP.w += w0 * v0.w + w1 * v1.w + w2 * v2.w + w3 * v3.w;
            }
        }
        __stcs(&outp[(gP + 0) * HW_ + t], accP.x);
        __stcs(&outp[(gP + 1) * HW_ + t], accP.y);
        __stcs(&outp[(gP + 2) * HW_ + t], accP.z);
        __stcs(&outp[(gP + 3) * HW_ + t], accP.w);
    }
}

extern "C" void kernel_launch(void* const* d_in, const int* in_sizes, int n_in,
                              void* d_out, int out_size)
{
    const float* feat  = (const float*)d_in[0];   // [A*B, C, H, W] f32
    const float* trans = (const float*)d_in[1];   // [B, A, A, 4, 4] f32
    const int*   nag   = (const int*)d_in[2];     // [B, A] int32
    float* out = (float*)d_out;                   // [A*B, C, H, W] f32

    static int attr_set = 0;
    if (!attr_set) {
        cudaFuncSetAttribute(fuse_kernel,
                             cudaFuncAttributeMaxDynamicSharedMemorySize, SMEM_BYTES);
        attr_set = 1;
    }

    dim3 grid(C_ / CCHUNK, A_, B_);
    fuse_kernel<<<grid, 256, SMEM_BYTES>>>(feat, trans, nag, out);
}